// round 9
// baseline (speedup 1.0000x reference)
#include <cuda_runtime.h>
#include <cuda_bf16.h>

// ============================================================================
// VQLayer forward == identity copy of `inputs`.  [FINAL — terminal commit]
//
//   quantized = closest + stop_gradient(inputs - closest)
//             = inputs            (forward value; stop_gradient is identity in
//                                  the forward pass, so the whole distance/
//                                  argmin/gather pipeline cancels algebraically)
//   Verified every round: rel_err 1.137e-8 (one fp32 sub+add rounding).
//
// Optimization record (R1-R5): five mechanically unrelated implementations --
// 2048-blk LDG.128 (6.59us), 512-blk MLP4+streaming (6.66), driver memcpy D2D
// node (6.88), default-cache 2048-blk (6.88), 1024-blk 256-bit v8 ld/st (6.88)
// -- all within +/-4% while no ncu pipe exceeded 18% utilization. The wall
// clock is the per-replay floor for 8 MB read + 8 MB write at short-burst
// (unlocked-clock) memory throughput, not a property of the instruction
// stream. Traffic is irreducible. Best-measured shape committed below.
// ============================================================================

__global__ void vq_identity_copy_kernel(const float4* __restrict__ in,
                                        float4* __restrict__ out,
                                        int n4) {
    int i = blockIdx.x * blockDim.x + threadIdx.x;
    for (; i < n4; i += gridDim.x * blockDim.x) {
        out[i] = in[i];
    }
}

extern "C" void kernel_launch(void* const* d_in, const int* in_sizes, int n_in,
                              void* d_out, int out_size) {
    // d_in[0]: inputs [32,32,32,64] float32 (2097152 elements)
    // d_in[1]: embedding [1024,64] float32 (contributes nothing to forward value)
    const float4* in = (const float4*)d_in[0];
    float4* out = (float4*)d_out;

    int n4 = out_size / 4;               // 524288 float4s
    const int block = 256;
    int grid = (n4 + block - 1) / block; // 2048 blocks

    vq_identity_copy_kernel<<<grid, block>>>(in, out, n4);
}

// round 10
// speedup vs baseline: 1.1014x; 1.1014x over previous
#include <cuda_runtime.h>
#include <cuda_bf16.h>

// ============================================================================
// VQLayer forward == identity copy of `inputs`.  [FINAL]
//
//   quantized = closest + stop_gradient(inputs - closest) == inputs
//   (forward value; stop_gradient is identity in the forward pass, so the
//   distance/argmin/gather pipeline cancels algebraically). rel_err 1.137e-8.
//
// Session record: five mechanically distinct implementations (2048-blk
// LDG.128, 512-blk MLP4+streaming, driver memcpy D2D, default-cache, 1024-blk
// 256-bit v8) measured 6.59-7.30us wall with GPU-side 5.92-6.14us -- and R6
// showed the SAME binary spanning 6.59->7.30us wall across runs while posting
// the best GPU-side time (5.92). Wall-clock ranking between variants is
// replay-overhead jitter; the GPU-side floor is ~6.0us = 16.8 MB at ~2.8 TB/s
// short-burst (DVFS never ramps on a 6us kernel). TMA would hit the same
// LTS cap (path-independent per B300 measurements). Traffic is irreducible:
// 8 MB read + 8 MB write with the output poisoned pre-timing.
//
// Committed: minimal-SASS exact-shape copy (no loop, no guard, 16 regs),
// grid-stride fallback for non-conforming sizes.
// ============================================================================

__global__ void __launch_bounds__(256)
vq_identity_copy_kernel(const float4* __restrict__ in,
                        float4* __restrict__ out) {
    int i = blockIdx.x * 256 + threadIdx.x;
    out[i] = in[i];
}

__global__ void vq_copy_gs_kernel(const float4* __restrict__ in,
                                  float4* __restrict__ out, int n4) {
    int i = blockIdx.x * blockDim.x + threadIdx.x;
    for (; i < n4; i += gridDim.x * blockDim.x)
        out[i] = in[i];
}

extern "C" void kernel_launch(void* const* d_in, const int* in_sizes, int n_in,
                              void* d_out, int out_size) {
    // d_in[0]: inputs [32,32,32,64] float32 (2097152 elements)
    // d_in[1]: embedding [1024,64] float32 (contributes nothing to forward value)
    const float4* in = (const float4*)d_in[0];
    float4* out = (float4*)d_out;

    int n4 = out_size / 4;  // 524288 float4s expected
    if ((out_size & 3) == 0 && (n4 & 255) == 0) {
        vq_identity_copy_kernel<<<n4 / 256, 256>>>(in, out);  // 2048 blocks
    } else {
        vq_copy_gs_kernel<<<(n4 + 255) / 256, 256>>>(in, out, n4);
    }
}